// round 10
// baseline (speedup 1.0000x reference)
#include <cuda_runtime.h>
#include <cuda_bf16.h>
#include <cstdint>

// DifferentiableTopKSelector == per-row hard top-32 mask of raw scores
// (straight-through estimator is value-identical to hard_mask; `u` is dead).
//
// Round 8: LDG front-batched reads (R4's measured-good path) + TMA bulk
// stores from a persistently-zeroed smem mask buffer. R4's ceiling was the
// L1tex wavefront pipe carrying BOTH streams; moving the 128 MB write
// stream to the TMA engine frees it. Per row only the 32 winner elements
// are set, stored (32 KB bulk), then cleared — the buffer stays zero.

static constexpr int COLS = 8192;
static constexpr int NT   = 256;
static constexpr int VPT  = COLS / 4 / NT;   // 8 float4 per thread
static constexpr int CAP  = 256;
static constexpr int KSEL = 32;
static constexpr unsigned ROW_BYTES = COLS * 4;   // 32 KB
static constexpr int GRID = 740;                  // ~5 CTAs/SM * 148 SMs
#define GUESS 2.3f

__device__ __forceinline__ uint32_t smem_u32(const void* p) {
    uint32_t a;
    asm("{ .reg .u64 t; cvta.to.shared.u64 t, %1; cvt.u32.u64 %0, t; }"
        : "=r"(a) : "l"(p));
    return a;
}

__device__ __forceinline__ unsigned long long pack_key(float v, unsigned idx) {
    // v > GUESS > 0: float bits compare as unsigned. Inverted index makes
    // larger composite == (larger value, then smaller index) — exactly
    // jax.lax.top_k's stable tie-break.
    return ((unsigned long long)__float_as_uint(v) << 32)
         | (unsigned long long)(COLS - 1u - idx);
}

__device__ __forceinline__ float vmax4(float4 v) {
    return fmaxf(fmaxf(v.x, v.y), fmaxf(v.z, v.w));
}

__global__ void __launch_bounds__(NT)
topk_mask_kernel(const float* __restrict__ scores, float* __restrict__ out,
                 int rows) {
    __shared__ __align__(128) float mask[COLS];      // 32 KB, kept zeroed
    __shared__ unsigned long long  cand[CAP];        // 2 KB
    __shared__ unsigned            w[KSEL];
    __shared__ int                 s_cnt;

    const int t = threadIdx.x;

    // ---- one-time zero of the mask buffer ----
    {
        float4* m4 = (float4*)mask;
        const float4 z = make_float4(0.f, 0.f, 0.f, 0.f);
        #pragma unroll
        for (int it = 0; it < VPT; ++it)
            m4[t + it * NT] = z;
    }
    unsigned prev_idx = 0;      // per-thread (t<32): winner set last row

    const int stride = gridDim.x;
    for (int r = blockIdx.x; r < rows; r += stride) {
        const size_t rowoff = (size_t)r * COLS;
        const float4* in4 = (const float4*)(scores + rowoff);

        // ---- front-batched loads: 8 independent LDG.128 (MLP_p1 = 8) ----
        float4 v[VPT];
        #pragma unroll
        for (int it = 0; it < VPT; ++it)
            v[it] = __ldcs(in4 + t + it * NT);

        if (t == 0) s_cnt = 0;
        __syncthreads();                              // also covers prev rank

        // ---- candidate detection on registers ----
        float mx = vmax4(v[0]);
        #pragma unroll
        for (int it = 1; it < VPT; ++it)
            mx = fmaxf(mx, vmax4(v[it]));

        if (mx > GUESS) {
            #pragma unroll
            for (int it = 0; it < VPT; ++it) {
                if (vmax4(v[it]) > GUESS) {
                    unsigned long long loc[4];
                    int n = 0;
                    const unsigned base = (unsigned)((t + it * NT) * 4);
                    if (v[it].x > GUESS) loc[n++] = pack_key(v[it].x, base + 0u);
                    if (v[it].y > GUESS) loc[n++] = pack_key(v[it].y, base + 1u);
                    if (v[it].z > GUESS) loc[n++] = pack_key(v[it].z, base + 2u);
                    if (v[it].w > GUESS) loc[n++] = pack_key(v[it].w, base + 3u);
                    int slot = atomicAdd(&s_cnt, n);
                    for (int q = 0; q < n; ++q)
                        if (slot + q < CAP) cand[slot + q] = loc[q];
                }
            }
        }
        __syncthreads();
        const int cnt = s_cnt;

        if (cnt >= KSEL && cnt <= CAP) {
            // ---- exact stable rank; ranks unique -> direct slot write ----
            if (t < cnt) {
                const unsigned long long ci = cand[t];
                int rk = 0;
                #pragma unroll 4
                for (int j = 0; j < cnt; ++j)
                    rk += (cand[j] > ci);             // LDS.64 broadcast
                if (rk < KSEL)
                    w[rk] = COLS - 1u - (unsigned)(ci & 0xFFFFFFFFull);
            }
        } else if (t == 0) {
            // ---- exact serial fallback (correctness guard, ~never) ----
            float    bk[KSEL];
            unsigned bi[KSEL];
            #pragma unroll
            for (int i = 0; i < KSEL; ++i) { bk[i] = -INFINITY; bi[i] = 0u; }
            const float* rowp = scores + rowoff;
            for (int i = 0; i < COLS; ++i) {
                float vv = rowp[i];
                if (vv > bk[KSEL - 1]) {              // strict > == stable
                    int p = KSEL - 1;
                    while (p > 0 && vv > bk[p - 1]) {
                        bk[p] = bk[p - 1]; bi[p] = bi[p - 1]; --p;
                    }
                    bk[p] = vv; bi[p] = (unsigned)i;
                }
            }
            for (int i = 0; i < KSEL; ++i) w[i] = bi[i];
        }

        // ---- wait for the PREVIOUS TMA store to finish READING smem ----
        if (t == 0)
            asm volatile("cp.async.bulk.wait_group.read 0;" ::: "memory");
        __syncthreads();                              // w[] ready + drain seen

        // ---- update mask: clear last row's ones, set this row's ones ----
        if (t < KSEL) {
            mask[prev_idx] = 0.0f;
            unsigned mine = w[t];
            __syncwarp();                             // clear before set
            mask[mine] = 1.0f;
            prev_idx = mine;
        }
        __syncthreads();

        // ---- TMA bulk store: smem -> gmem, bypasses L1tex ----
        if (t == 0) {
            asm volatile("fence.proxy.async.shared::cta;" ::: "memory");
            asm volatile(
                "cp.async.bulk.global.shared::cta.bulk_group [%0], [%1], %2;"
                :: "l"(out + rowoff), "r"(smem_u32(mask)), "r"(ROW_BYTES)
                : "memory");
            asm volatile("cp.async.bulk.commit_group;" ::: "memory");
        }
    }

    // full drain before CTA exit (global writes must be committed)
    if (t == 0)
        asm volatile("cp.async.bulk.wait_group 0;" ::: "memory");
}

extern "C" void kernel_launch(void* const* d_in, const int* in_sizes, int n_in,
                              void* d_out, int out_size) {
    const float* scores = (const float*)d_in[0];   // (4096, 8192) fp32
    // d_in[1] (u) is mathematically dead: output == hard top-k mask of scores.
    float* out = (float*)d_out;
    const int rows = out_size / COLS;              // 4096
    const int grid = (rows < GRID) ? rows : GRID;
    topk_mask_kernel<<<grid, NT>>>(scores, out, rows);
}

// round 11
// speedup vs baseline: 1.5716x; 1.5716x over previous
#include <cuda_runtime.h>
#include <cuda_bf16.h>
#include <cstdint>

// DifferentiableTopKSelector == per-row hard top-32 mask of raw scores
// (straight-through estimator is value-identical to hard_mask; `u` is dead).
//
// Round 11: R4 skeleton (front-batched LDG.128 reads + inline STG.128 zero
// stores, guess-threshold candidate gather, exact stable rank on ~88
// composite keys) with the occupancy fixed: NT=512 / VPT=4 / 32-reg cap
// gives 4 CTAs/SM = 64 warps (R4: 40). Both TMA variants (R5-R10) measured
// slower; the plain LDG/STG path with high occupancy is the winner shape.

static constexpr int COLS = 8192;
static constexpr int NT   = 512;
static constexpr int VPT  = COLS / 4 / NT;   // 4 float4 per thread
static constexpr int CAP  = 256;
static constexpr int KSEL = 32;
#define GUESS 2.3f

__device__ __forceinline__ unsigned long long pack_key(float v, unsigned idx) {
    // v > GUESS > 0: float bits compare as unsigned. Inverted index makes
    // larger composite == (larger value, then smaller index) — exactly
    // jax.lax.top_k's stable tie-break.
    return ((unsigned long long)__float_as_uint(v) << 32)
         | (unsigned long long)(COLS - 1u - idx);
}

__device__ __forceinline__ float vmax4(float4 v) {
    return fmaxf(fmaxf(v.x, v.y), fmaxf(v.z, v.w));
}

__global__ void __launch_bounds__(NT, 4)
topk_mask_kernel(const float* __restrict__ scores, float* __restrict__ out) {
    __shared__ unsigned long long cand[CAP];   // 2 KB
    __shared__ int s_cnt;

    const int t = threadIdx.x;
    if (t == 0) s_cnt = 0;
    __syncthreads();

    const size_t rowoff = (size_t)blockIdx.x * (size_t)COLS;
    const float4* in4  = (const float4*)(scores + rowoff);
    float4*       out4 = (float4*)(out + rowoff);
    const float4  zero4 = make_float4(0.f, 0.f, 0.f, 0.f);

    // ---- phase 1: all 4 loads issued back-to-back (front-batched MLP) ----
    float4 v[VPT];
    #pragma unroll
    for (int it = 0; it < VPT; ++it)
        v[it] = __ldcs(in4 + t + it * NT);

    // ---- phase 2: zero fill (independent of load results) ----
    #pragma unroll
    for (int it = 0; it < VPT; ++it)
        __stcs(out4 + t + it * NT, zero4);

    // ---- phase 3: candidate detection on registers ----
    float mx = vmax4(v[0]);
    #pragma unroll
    for (int it = 1; it < VPT; ++it)
        mx = fmaxf(mx, vmax4(v[it]));

    if (mx > GUESS) {                       // ~16% of threads at VPT=4
        #pragma unroll
        for (int it = 0; it < VPT; ++it) {
            if (vmax4(v[it]) > GUESS) {
                unsigned long long loc[4];
                int n = 0;
                const unsigned base = (unsigned)((t + it * NT) * 4);
                if (v[it].x > GUESS) loc[n++] = pack_key(v[it].x, base + 0u);
                if (v[it].y > GUESS) loc[n++] = pack_key(v[it].y, base + 1u);
                if (v[it].z > GUESS) loc[n++] = pack_key(v[it].z, base + 2u);
                if (v[it].w > GUESS) loc[n++] = pack_key(v[it].w, base + 3u);
                int slot = atomicAdd(&s_cnt, n);
                for (int q = 0; q < n; ++q)
                    if (slot + q < CAP) cand[slot + q] = loc[q];
            }
        }
    }
    __syncthreads();

    const int cnt = s_cnt;

    if (cnt >= KSEL && cnt <= CAP) {
        // ---- exact stable rank among candidates; scatter the 32 ones ----
        if (t < cnt) {
            const unsigned long long ci = cand[t];
            int r = 0;
            #pragma unroll 4
            for (int j = 0; j < cnt; ++j)
                r += (cand[j] > ci);                 // LDS.64 broadcast
            if (r < KSEL) {
                unsigned idx = COLS - 1u - (unsigned)(ci & 0xFFFFFFFFull);
                out[rowoff + idx] = 1.0f;
            }
        }
    } else if (t == 0) {
        // ---- exact serial fallback (correctness guard; never taken for
        //      N(0,1) rows — 6-sigma event). Arrays live in local mem. ----
        float    bk[KSEL];
        unsigned bi[KSEL];
        #pragma unroll
        for (int i = 0; i < KSEL; ++i) { bk[i] = -INFINITY; bi[i] = 0u; }
        const float* rowp = scores + rowoff;
        for (int i = 0; i < COLS; ++i) {
            float vv = rowp[i];
            if (vv > bk[KSEL - 1]) {                 // strict > == stable
                int p = KSEL - 1;
                while (p > 0 && vv > bk[p - 1]) {
                    bk[p] = bk[p - 1]; bi[p] = bi[p - 1]; --p;
                }
                bk[p] = vv; bi[p] = (unsigned)i;
            }
        }
        for (int i = 0; i < KSEL; ++i)
            out[rowoff + bi[i]] = 1.0f;
    }
}

extern "C" void kernel_launch(void* const* d_in, const int* in_sizes, int n_in,
                              void* d_out, int out_size) {
    const float* scores = (const float*)d_in[0];   // (4096, 8192) fp32
    // d_in[1] (u) is mathematically dead: output == hard top-k mask of scores.
    float* out = (float*)d_out;
    const int rows = out_size / COLS;              // 4096
    topk_mask_kernel<<<rows, NT>>>(scores, out);
}